// round 2
// baseline (speedup 1.0000x reference)
#include <cuda_runtime.h>
#include <cstdint>
#include <cstddef>

#define TB 256
#define BATCH 256
#define TENC 200
#define TD 200
#define DMODEL 256
#define INR 400

// ------------------------- persistent device scratch -------------------------
__device__ float g_pm[BATCH * TENC * DMODEL];      // processed_memory  (52 MB)
__device__ float g_Wp1T[400 * 256];
__device__ float g_Wp2T[256 * 128];
__device__ float g_WaihT[384 * 768];
__device__ float g_WahhT[256 * 768];
__device__ float g_WmemT[256 * 256];
__device__ float g_WqT[256 * 256];
__device__ float g_WprojT[512 * 256];
__device__ float g_Wd1iT[256 * 768];
__device__ float g_Wd1hT[256 * 768];
__device__ float g_Wd2iT[256 * 768];
__device__ float g_Wd2hT[256 * 768];
__device__ float g_WmelT[256 * 400];

// ------------------------- helpers -------------------------
__device__ __forceinline__ float tanh_approx(float x) {
    float y;
    asm("tanh.approx.f32 %0, %1;" : "=f"(y) : "f"(x));
    return y;
}
__device__ __forceinline__ float sigmoidf_(float x) {
    return 1.0f / (1.0f + __expf(-x));
}

// W is [O,K] row-major; WT is [K,O]: WT[k*O+o] = W[o*K+k]
__global__ void transpose_kernel(const float* __restrict__ src, float* __restrict__ dst,
                                 int O, int K) {
    int idx = blockIdx.x * blockDim.x + threadIdx.x;
    if (idx < O * K) {
        int o = idx / K;
        int k = idx - o * K;
        dst[k * O + o] = src[idx];
    }
}

// y[r][o] = act( sum_k WT[k][o] * x_r[k] + bias[o] )  for r in {0,1}
// WT layout [K,O]; coalesced float2 weight loads, float4 smem x loads.
template <int O, int K, int RELU>
__device__ __forceinline__ void gemv2(const float* __restrict__ WT,
                                      const float* __restrict__ x0,
                                      const float* __restrict__ x1,
                                      const float* __restrict__ bias,
                                      float* __restrict__ y0,
                                      float* __restrict__ y1) {
    constexpr int G = O / 2;
    const float2* __restrict__ W2 = reinterpret_cast<const float2*>(WT);
    const float4* __restrict__ X0 = reinterpret_cast<const float4*>(x0);
    const float4* __restrict__ X1 = reinterpret_cast<const float4*>(x1);
    for (int g = threadIdx.x; g < G; g += TB) {
        float a0 = 0.f, a1 = 0.f, b0 = 0.f, b1 = 0.f;
#pragma unroll 2
        for (int k4 = 0; k4 < K / 4; ++k4) {
            float4 xa = X0[k4];
            float4 xb = X1[k4];
            float2 w0 = W2[(k4 * 4 + 0) * G + g];
            float2 w1 = W2[(k4 * 4 + 1) * G + g];
            float2 w2 = W2[(k4 * 4 + 2) * G + g];
            float2 w3 = W2[(k4 * 4 + 3) * G + g];
            a0 = fmaf(w0.x, xa.x, a0); a1 = fmaf(w0.y, xa.x, a1);
            b0 = fmaf(w0.x, xb.x, b0); b1 = fmaf(w0.y, xb.x, b1);
            a0 = fmaf(w1.x, xa.y, a0); a1 = fmaf(w1.y, xa.y, a1);
            b0 = fmaf(w1.x, xb.y, b0); b1 = fmaf(w1.y, xb.y, b1);
            a0 = fmaf(w2.x, xa.z, a0); a1 = fmaf(w2.y, xa.z, a1);
            b0 = fmaf(w2.x, xb.z, b0); b1 = fmaf(w2.y, xb.z, b1);
            a0 = fmaf(w3.x, xa.w, a0); a1 = fmaf(w3.y, xa.w, a1);
            b0 = fmaf(w3.x, xb.w, b0); b1 = fmaf(w3.y, xb.w, b1);
        }
        if (bias) {
            float bb0 = bias[2 * g], bb1 = bias[2 * g + 1];
            a0 += bb0; a1 += bb1; b0 += bb0; b1 += bb1;
        }
        if (RELU) {
            a0 = fmaxf(a0, 0.f); a1 = fmaxf(a1, 0.f);
            b0 = fmaxf(b0, 0.f); b1 = fmaxf(b1, 0.f);
        }
        y0[2 * g] = a0; y0[2 * g + 1] = a1;
        y1[2 * g] = b0; y1[2 * g + 1] = b1;
    }
}

// processed_memory: pm[row] = mem_W @ enc[row], 2 rows per block
__global__ void __launch_bounds__(TB) pm_kernel(const float* __restrict__ enc,
                                                float* __restrict__ pm) {
    __shared__ __align__(16) float x0[DMODEL];
    __shared__ __align__(16) float x1[DMODEL];
    size_t row0 = (size_t)blockIdx.x * 2;
    const float* e = enc + row0 * DMODEL;
    for (int i = threadIdx.x; i < DMODEL; i += TB) {
        x0[i] = e[i];
        x1[i] = e[DMODEL + i];
    }
    __syncthreads();
    gemv2<256, 256, 0>(g_WmemT, x0, x1, nullptr, pm + row0 * DMODEL,
                       pm + row0 * DMODEL + DMODEL);
}

// ------------------------- main persistent decoder -------------------------
__global__ void __launch_bounds__(TB) decoder_kernel(
    const float* __restrict__ enc, const float* __restrict__ inputs,
    const int* __restrict__ memlen,
    const float* __restrict__ b_p1, const float* __restrict__ b_p2,
    const float* __restrict__ b_aih, const float* __restrict__ b_ahh,
    const float* __restrict__ vW,
    const float* __restrict__ b_proj,
    const float* __restrict__ b_d1i, const float* __restrict__ b_d1h,
    const float* __restrict__ b_d2i, const float* __restrict__ b_d2h,
    const float* __restrict__ b_mel,
    float* __restrict__ out, int write_align) {
    __shared__ __align__(16) float s_in[2][400];
    __shared__ __align__(16) float s_p1[2][256];
    __shared__ __align__(16) float s_x[2][384];   // [0:128)=prenet2, [128:384)=attention ctx
    __shared__ __align__(16) float s_ah[2][256];  // attention GRU hidden
    __shared__ __align__(16) float s_h1[2][256];
    __shared__ __align__(16) float s_h2[2][256];
    __shared__ __align__(16) float s_q[2][256];
    __shared__ __align__(16) float s_gi[2][768];
    __shared__ __align__(16) float s_gh[2][768];
    __shared__ __align__(16) float s_cat[2][512];
    __shared__ __align__(16) float s_d[2][256];
    __shared__ __align__(16) float s_sc[2][TENC];
    __shared__ __align__(16) float s_v[256];

    const int tid = threadIdx.x;
    const int b0 = blockIdx.x * 2;
    const int len0 = memlen[b0];
    const int len1 = memlen[b0 + 1];

    for (int i = tid; i < 256; i += TB) {
        s_ah[0][i] = 0.f; s_ah[1][i] = 0.f;
        s_h1[0][i] = 0.f; s_h1[1][i] = 0.f;
        s_h2[0][i] = 0.f; s_h2[1][i] = 0.f;
        s_x[0][128 + i] = 0.f; s_x[1][128 + i] = 0.f;
        s_v[i] = vW[i];
    }
    __syncthreads();

    float* outMel = out;
    float* outAl = out + (size_t)BATCH * TD * INR;

    for (int t = 0; t < TD; ++t) {
        // teacher-forced input (previous target frame group, zeros at t=0)
        if (t == 0) {
            for (int i = tid; i < INR; i += TB) { s_in[0][i] = 0.f; s_in[1][i] = 0.f; }
        } else {
            const float* p0 = inputs + ((size_t)b0 * 1000 + (size_t)(t - 1) * 5) * 80;
            const float* p1 = inputs + ((size_t)(b0 + 1) * 1000 + (size_t)(t - 1) * 5) * 80;
            for (int i = tid; i < INR; i += TB) { s_in[0][i] = p0[i]; s_in[1][i] = p1[i]; }
        }
        __syncthreads();

        // prenet
        gemv2<256, 400, 1>(g_Wp1T, s_in[0], s_in[1], b_p1, s_p1[0], s_p1[1]);
        __syncthreads();
        gemv2<128, 256, 1>(g_Wp2T, s_p1[0], s_p1[1], b_p2, s_x[0], s_x[1]);
        __syncthreads();

        // attention GRU (input = [prenet(128), attention(256)] = s_x)
        gemv2<768, 384, 0>(g_WaihT, s_x[0], s_x[1], b_aih, s_gi[0], s_gi[1]);
        gemv2<768, 256, 0>(g_WahhT, s_ah[0], s_ah[1], b_ahh, s_gh[0], s_gh[1]);
        __syncthreads();
        for (int idx = tid; idx < 512; idx += TB) {
            int r = idx >> 8, o = idx & 255;
            float rg = sigmoidf_(s_gi[r][o] + s_gh[r][o]);
            float z = sigmoidf_(s_gi[r][256 + o] + s_gh[r][256 + o]);
            float n = tanhf(s_gi[r][512 + o] + rg * s_gh[r][512 + o]);
            s_ah[r][o] = (1.f - z) * n + z * s_ah[r][o];
        }
        __syncthreads();

        // query projection
        gemv2<256, 256, 0>(g_WqT, s_ah[0], s_ah[1], nullptr, s_q[0], s_q[1]);
        __syncthreads();

        // Bahdanau scores: s = v . tanh(pm + q)
        {
            int wid = tid >> 5, lane = tid & 31;
            for (int task = wid; task < 2 * TENC; task += 8) {
                int r = task & 1, tt = task >> 1;
                const float4* P = reinterpret_cast<const float4*>(
                    g_pm + ((size_t)(b0 + r) * TENC + tt) * DMODEL);
                const float4* Q = reinterpret_cast<const float4*>(s_q[r]);
                const float4* V = reinterpret_cast<const float4*>(s_v);
                float acc = 0.f;
#pragma unroll
                for (int u = 0; u < 2; ++u) {
                    int k4 = u * 32 + lane;
                    float4 p = P[k4], q = Q[k4], v = V[k4];
                    acc += v.x * tanh_approx(p.x + q.x);
                    acc += v.y * tanh_approx(p.y + q.y);
                    acc += v.z * tanh_approx(p.z + q.z);
                    acc += v.w * tanh_approx(p.w + q.w);
                }
#pragma unroll
                for (int s = 16; s; s >>= 1) acc += __shfl_xor_sync(0xffffffffu, acc, s);
                if (lane == 0) {
                    int L = r ? len1 : len0;
                    s_sc[r][tt] = (tt < L) ? acc : -1e9f;
                }
            }
        }
        __syncthreads();

        // softmax + alignments output
        {
            int wid = tid >> 5, lane = tid & 31;
            if (wid < 2) {
                int r = wid;
                float m = -1e30f;
                for (int i = lane; i < TENC; i += 32) m = fmaxf(m, s_sc[r][i]);
#pragma unroll
                for (int s = 16; s; s >>= 1) m = fmaxf(m, __shfl_xor_sync(0xffffffffu, m, s));
                float sum = 0.f;
                for (int i = lane; i < TENC; i += 32) {
                    float e = __expf(s_sc[r][i] - m);
                    s_sc[r][i] = e;
                    sum += e;
                }
#pragma unroll
                for (int s = 16; s; s >>= 1) sum += __shfl_xor_sync(0xffffffffu, sum, s);
                float inv = 1.f / sum;
                float* ao = outAl + ((size_t)(b0 + r) * TD + t) * TENC;
                for (int i = lane; i < TENC; i += 32) {
                    float a = s_sc[r][i] * inv;
                    s_sc[r][i] = a;
                    if (write_align) ao[i] = a;
                }
            }
        }
        __syncthreads();

        // attention context + build [attn_h, ctx] concat
        {
            int o = tid;
            float c0 = 0.f, c1 = 0.f;
            const float* e0 = enc + (size_t)b0 * TENC * DMODEL + o;
            const float* e1 = e0 + (size_t)TENC * DMODEL;
#pragma unroll 4
            for (int tt = 0; tt < TENC; ++tt) {
                c0 = fmaf(s_sc[0][tt], e0[(size_t)tt * DMODEL], c0);
                c1 = fmaf(s_sc[1][tt], e1[(size_t)tt * DMODEL], c1);
            }
            s_x[0][128 + o] = c0; s_x[1][128 + o] = c1;
            s_cat[0][256 + o] = c0; s_cat[1][256 + o] = c1;
            s_cat[0][o] = s_ah[0][o]; s_cat[1][o] = s_ah[1][o];
        }
        __syncthreads();

        // project to decoder input
        gemv2<256, 512, 0>(g_WprojT, s_cat[0], s_cat[1], b_proj, s_d[0], s_d[1]);
        __syncthreads();

        // decoder GRU 1 (+ residual)
        gemv2<768, 256, 0>(g_Wd1iT, s_d[0], s_d[1], b_d1i, s_gi[0], s_gi[1]);
        gemv2<768, 256, 0>(g_Wd1hT, s_h1[0], s_h1[1], b_d1h, s_gh[0], s_gh[1]);
        __syncthreads();
        for (int idx = tid; idx < 512; idx += TB) {
            int r = idx >> 8, o = idx & 255;
            float rg = sigmoidf_(s_gi[r][o] + s_gh[r][o]);
            float z = sigmoidf_(s_gi[r][256 + o] + s_gh[r][256 + o]);
            float n = tanhf(s_gi[r][512 + o] + rg * s_gh[r][512 + o]);
            s_h1[r][o] = (1.f - z) * n + z * s_h1[r][o];
        }
        __syncthreads();
        for (int idx = tid; idx < 512; idx += TB) {
            int r = idx >> 8, o = idx & 255;
            s_d[r][o] += s_h1[r][o];
        }
        __syncthreads();

        // decoder GRU 2 (+ residual)
        gemv2<768, 256, 0>(g_Wd2iT, s_d[0], s_d[1], b_d2i, s_gi[0], s_gi[1]);
        gemv2<768, 256, 0>(g_Wd2hT, s_h2[0], s_h2[1], b_d2h, s_gh[0], s_gh[1]);
        __syncthreads();
        for (int idx = tid; idx < 512; idx += TB) {
            int r = idx >> 8, o = idx & 255;
            float rg = sigmoidf_(s_gi[r][o] + s_gh[r][o]);
            float z = sigmoidf_(s_gi[r][256 + o] + s_gh[r][256 + o]);
            float n = tanhf(s_gi[r][512 + o] + rg * s_gh[r][512 + o]);
            s_h2[r][o] = (1.f - z) * n + z * s_h2[r][o];
        }
        __syncthreads();
        for (int idx = tid; idx < 512; idx += TB) {
            int r = idx >> 8, o = idx & 255;
            s_d[r][o] += s_h2[r][o];
        }
        __syncthreads();

        // mel projection -> straight to global output
        gemv2<400, 256, 0>(g_WmelT, s_d[0], s_d[1], b_mel,
                           outMel + ((size_t)b0 * TD + t) * INR,
                           outMel + ((size_t)(b0 + 1) * TD + t) * INR);
        __syncthreads();
    }
}

// ------------------------- launch -------------------------
extern "C" void kernel_launch(void* const* d_in, const int* in_sizes, int n_in,
                              void* d_out, int out_size) {
    const float* enc = (const float*)d_in[0];
    const float* inputs = (const float*)d_in[1];
    const int* memlen = (const int*)d_in[2];

    float *pWp1T, *pWp2T, *pWaihT, *pWahhT, *pWmemT, *pWqT, *pWprojT;
    float *pWd1iT, *pWd1hT, *pWd2iT, *pWd2hT, *pWmelT, *pPm;
    cudaGetSymbolAddress((void**)&pWp1T, g_Wp1T);
    cudaGetSymbolAddress((void**)&pWp2T, g_Wp2T);
    cudaGetSymbolAddress((void**)&pWaihT, g_WaihT);
    cudaGetSymbolAddress((void**)&pWahhT, g_WahhT);
    cudaGetSymbolAddress((void**)&pWmemT, g_WmemT);
    cudaGetSymbolAddress((void**)&pWqT, g_WqT);
    cudaGetSymbolAddress((void**)&pWprojT, g_WprojT);
    cudaGetSymbolAddress((void**)&pWd1iT, g_Wd1iT);
    cudaGetSymbolAddress((void**)&pWd1hT, g_Wd1hT);
    cudaGetSymbolAddress((void**)&pWd2iT, g_Wd2iT);
    cudaGetSymbolAddress((void**)&pWd2hT, g_Wd2hT);
    cudaGetSymbolAddress((void**)&pWmelT, g_WmelT);
    cudaGetSymbolAddress((void**)&pPm, g_pm);

    auto T = [&](const void* src, float* dst, int O, int K) {
        transpose_kernel<<<(O * K + 255) / 256, 256>>>((const float*)src, dst, O, K);
    };
    T(d_in[3], pWp1T, 256, 400);    // prenet_W1
    T(d_in[5], pWp2T, 128, 256);    // prenet_W2
    T(d_in[7], pWaihT, 768, 384);   // attn_Wih
    T(d_in[9], pWahhT, 768, 256);   // attn_Whh
    T(d_in[11], pWmemT, 256, 256);  // mem_W
    T(d_in[12], pWqT, 256, 256);    // query_W
    T(d_in[14], pWprojT, 256, 512); // proj_in_W
    T(d_in[16], pWd1iT, 768, 256);  // dec1_Wih
    T(d_in[18], pWd1hT, 768, 256);  // dec1_Whh
    T(d_in[20], pWd2iT, 768, 256);  // dec2_Wih
    T(d_in[22], pWd2hT, 768, 256);  // dec2_Whh
    T(d_in[24], pWmelT, 400, 256);  // mel_W

    pm_kernel<<<BATCH * TENC / 2, TB>>>(enc, pPm);

    int write_align = (out_size >= BATCH * TD * (INR + TENC)) ? 1 : 0;

    decoder_kernel<<<BATCH / 2, TB>>>(
        enc, inputs, memlen,
        (const float*)d_in[4], (const float*)d_in[6],
        (const float*)d_in[8], (const float*)d_in[10],
        (const float*)d_in[13],
        (const float*)d_in[15],
        (const float*)d_in[17], (const float*)d_in[19],
        (const float*)d_in[21], (const float*)d_in[23],
        (const float*)d_in[25],
        (float*)d_out, write_align);
}

// round 3
// speedup vs baseline: 1.0229x; 1.0229x over previous
#include <cuda_runtime.h>
#include <cstdint>
#include <cstddef>

#define TB 256
#define BATCH 256
#define TENC 200
#define TD 200
#define DMODEL 256
#define INR 400

// ------------------------- persistent device scratch -------------------------
__device__ float g_pm[BATCH * TENC * DMODEL];      // processed_memory  (52 MB)
__device__ float g_Wp1T[400 * 256];
__device__ float g_Wp2T[256 * 128];
__device__ float g_WaihT[384 * 768];
__device__ float g_WahhT[256 * 768];
__device__ float g_WmemT[256 * 256];
__device__ float g_WqT[256 * 256];
__device__ float g_WprojT[512 * 256];
__device__ float g_Wd1iT[256 * 768];
__device__ float g_Wd1hT[256 * 768];
__device__ float g_Wd2iT[256 * 768];
__device__ float g_Wd2hT[256 * 768];
__device__ float g_WmelT[256 * 400];

// ------------------------- helpers -------------------------
__device__ __forceinline__ float tanh_approx(float x) {
    float y;
    asm("tanh.approx.f32 %0, %1;" : "=f"(y) : "f"(x));
    return y;
}
__device__ __forceinline__ float sigmoidf_(float x) {
    return 1.0f / (1.0f + __expf(-x));
}

// W is [O,K] row-major; WT is [K,O]: WT[k*O+o] = W[o*K+k]
__global__ void transpose_kernel(const float* __restrict__ src, float* __restrict__ dst,
                                 int O, int K) {
    int idx = blockIdx.x * blockDim.x + threadIdx.x;
    if (idx < O * K) {
        int o = idx / K;
        int k = idx - o * K;
        dst[k * O + o] = src[idx];
    }
}

// y[r][o] = act( sum_k WT[k][o] * x_r[k] + bias[o] )  for r in {0,1}
// WT layout [K,O]; coalesced float2 weight loads, float4 smem x loads.
template <int O, int K, int RELU>
__device__ __forceinline__ void gemv2(const float* __restrict__ WT,
                                      const float* __restrict__ x0,
                                      const float* __restrict__ x1,
                                      const float* __restrict__ bias,
                                      float* __restrict__ y0,
                                      float* __restrict__ y1) {
    constexpr int G = O / 2;
    const float2* __restrict__ W2 = reinterpret_cast<const float2*>(WT);
    const float4* __restrict__ X0 = reinterpret_cast<const float4*>(x0);
    const float4* __restrict__ X1 = reinterpret_cast<const float4*>(x1);
    for (int g = threadIdx.x; g < G; g += TB) {
        float a0 = 0.f, a1 = 0.f, b0 = 0.f, b1 = 0.f;
#pragma unroll 2
        for (int k4 = 0; k4 < K / 4; ++k4) {
            float4 xa = X0[k4];
            float4 xb = X1[k4];
            float2 w0 = W2[(k4 * 4 + 0) * G + g];
            float2 w1 = W2[(k4 * 4 + 1) * G + g];
            float2 w2 = W2[(k4 * 4 + 2) * G + g];
            float2 w3 = W2[(k4 * 4 + 3) * G + g];
            a0 = fmaf(w0.x, xa.x, a0); a1 = fmaf(w0.y, xa.x, a1);
            b0 = fmaf(w0.x, xb.x, b0); b1 = fmaf(w0.y, xb.x, b1);
            a0 = fmaf(w1.x, xa.y, a0); a1 = fmaf(w1.y, xa.y, a1);
            b0 = fmaf(w1.x, xb.y, b0); b1 = fmaf(w1.y, xb.y, b1);
            a0 = fmaf(w2.x, xa.z, a0); a1 = fmaf(w2.y, xa.z, a1);
            b0 = fmaf(w2.x, xb.z, b0); b1 = fmaf(w2.y, xb.z, b1);
            a0 = fmaf(w3.x, xa.w, a0); a1 = fmaf(w3.y, xa.w, a1);
            b0 = fmaf(w3.x, xb.w, b0); b1 = fmaf(w3.y, xb.w, b1);
        }
        if (bias) {
            float bb0 = bias[2 * g], bb1 = bias[2 * g + 1];
            a0 += bb0; a1 += bb1; b0 += bb0; b1 += bb1;
        }
        if (RELU) {
            a0 = fmaxf(a0, 0.f); a1 = fmaxf(a1, 0.f);
            b0 = fmaxf(b0, 0.f); b1 = fmaxf(b1, 0.f);
        }
        y0[2 * g] = a0; y0[2 * g + 1] = a1;
        y1[2 * g] = b0; y1[2 * g + 1] = b1;
    }
}

// processed_memory: pm[row] = mem_W @ enc[row], 2 rows per block
__global__ void __launch_bounds__(TB) pm_kernel(const float* __restrict__ enc,
                                                float* __restrict__ pm) {
    __shared__ __align__(16) float x0[DMODEL];
    __shared__ __align__(16) float x1[DMODEL];
    size_t row0 = (size_t)blockIdx.x * 2;
    const float* e = enc + row0 * DMODEL;
    for (int i = threadIdx.x; i < DMODEL; i += TB) {
        x0[i] = e[i];
        x1[i] = e[DMODEL + i];
    }
    __syncthreads();
    gemv2<256, 256, 0>(g_WmemT, x0, x1, nullptr, pm + row0 * DMODEL,
                       pm + row0 * DMODEL + DMODEL);
}

// ------------------------- main persistent decoder -------------------------
__global__ void __launch_bounds__(TB) decoder_kernel(
    const float* __restrict__ enc, const float* __restrict__ inputs,
    const int* __restrict__ memlen,
    const float* __restrict__ b_p1, const float* __restrict__ b_p2,
    const float* __restrict__ b_aih, const float* __restrict__ b_ahh,
    const float* __restrict__ vW,
    const float* __restrict__ b_proj,
    const float* __restrict__ b_d1i, const float* __restrict__ b_d1h,
    const float* __restrict__ b_d2i, const float* __restrict__ b_d2h,
    const float* __restrict__ b_mel,
    float* __restrict__ out, int write_align) {
    __shared__ __align__(16) float s_in[2][400];
    __shared__ __align__(16) float s_p1[2][256];
    __shared__ __align__(16) float s_x[2][384];   // [0:128)=prenet2, [128:384)=attention ctx
    __shared__ __align__(16) float s_ah[2][256];  // attention GRU hidden
    __shared__ __align__(16) float s_h1[2][256];
    __shared__ __align__(16) float s_h2[2][256];
    __shared__ __align__(16) float s_q[2][256];
    __shared__ __align__(16) float s_gi[2][768];
    __shared__ __align__(16) float s_gh[2][768];
    __shared__ __align__(16) float s_cat[2][512];
    __shared__ __align__(16) float s_d[2][256];
    __shared__ __align__(16) float s_sc[2][TENC];
    __shared__ __align__(16) float s_v[256];

    const int tid = threadIdx.x;
    const int b0 = blockIdx.x * 2;
    const int len0 = memlen[b0];
    const int len1 = memlen[b0 + 1];

    for (int i = tid; i < 256; i += TB) {
        s_ah[0][i] = 0.f; s_ah[1][i] = 0.f;
        s_h1[0][i] = 0.f; s_h1[1][i] = 0.f;
        s_h2[0][i] = 0.f; s_h2[1][i] = 0.f;
        s_x[0][128 + i] = 0.f; s_x[1][128 + i] = 0.f;
        s_v[i] = vW[i];
    }
    __syncthreads();

    float* outMel = out;
    float* outAl = out + (size_t)BATCH * TD * INR;

    for (int t = 0; t < TD; ++t) {
        // teacher-forced input (previous target frame group, zeros at t=0)
        if (t == 0) {
            for (int i = tid; i < INR; i += TB) { s_in[0][i] = 0.f; s_in[1][i] = 0.f; }
        } else {
            const float* p0 = inputs + ((size_t)b0 * 1000 + (size_t)(t - 1) * 5) * 80;
            const float* p1 = inputs + ((size_t)(b0 + 1) * 1000 + (size_t)(t - 1) * 5) * 80;
            for (int i = tid; i < INR; i += TB) { s_in[0][i] = p0[i]; s_in[1][i] = p1[i]; }
        }
        __syncthreads();

        // prenet
        gemv2<256, 400, 1>(g_Wp1T, s_in[0], s_in[1], b_p1, s_p1[0], s_p1[1]);
        __syncthreads();
        gemv2<128, 256, 1>(g_Wp2T, s_p1[0], s_p1[1], b_p2, s_x[0], s_x[1]);
        __syncthreads();

        // attention GRU (input = [prenet(128), attention(256)] = s_x)
        gemv2<768, 384, 0>(g_WaihT, s_x[0], s_x[1], b_aih, s_gi[0], s_gi[1]);
        gemv2<768, 256, 0>(g_WahhT, s_ah[0], s_ah[1], b_ahh, s_gh[0], s_gh[1]);
        __syncthreads();
        for (int idx = tid; idx < 512; idx += TB) {
            int r = idx >> 8, o = idx & 255;
            float rg = sigmoidf_(s_gi[r][o] + s_gh[r][o]);
            float z = sigmoidf_(s_gi[r][256 + o] + s_gh[r][256 + o]);
            float n = tanhf(s_gi[r][512 + o] + rg * s_gh[r][512 + o]);
            s_ah[r][o] = (1.f - z) * n + z * s_ah[r][o];
        }
        __syncthreads();

        // query projection
        gemv2<256, 256, 0>(g_WqT, s_ah[0], s_ah[1], nullptr, s_q[0], s_q[1]);
        __syncthreads();

        // Bahdanau scores: s = v . tanh(pm + q)
        {
            int wid = tid >> 5, lane = tid & 31;
            for (int task = wid; task < 2 * TENC; task += 8) {
                int r = task & 1, tt = task >> 1;
                const float4* P = reinterpret_cast<const float4*>(
                    g_pm + ((size_t)(b0 + r) * TENC + tt) * DMODEL);
                const float4* Q = reinterpret_cast<const float4*>(s_q[r]);
                const float4* V = reinterpret_cast<const float4*>(s_v);
                float acc = 0.f;
#pragma unroll
                for (int u = 0; u < 2; ++u) {
                    int k4 = u * 32 + lane;
                    float4 p = P[k4], q = Q[k4], v = V[k4];
                    acc += v.x * tanh_approx(p.x + q.x);
                    acc += v.y * tanh_approx(p.y + q.y);
                    acc += v.z * tanh_approx(p.z + q.z);
                    acc += v.w * tanh_approx(p.w + q.w);
                }
#pragma unroll
                for (int s = 16; s; s >>= 1) acc += __shfl_xor_sync(0xffffffffu, acc, s);
                if (lane == 0) {
                    int L = r ? len1 : len0;
                    s_sc[r][tt] = (tt < L) ? acc : -1e9f;
                }
            }
        }
        __syncthreads();

        // softmax + alignments output
        {
            int wid = tid >> 5, lane = tid & 31;
            if (wid < 2) {
                int r = wid;
                float m = -1e30f;
                for (int i = lane; i < TENC; i += 32) m = fmaxf(m, s_sc[r][i]);
#pragma unroll
                for (int s = 16; s; s >>= 1) m = fmaxf(m, __shfl_xor_sync(0xffffffffu, m, s));
                float sum = 0.f;
                for (int i = lane; i < TENC; i += 32) {
                    float e = __expf(s_sc[r][i] - m);
                    s_sc[r][i] = e;
                    sum += e;
                }
#pragma unroll
                for (int s = 16; s; s >>= 1) sum += __shfl_xor_sync(0xffffffffu, sum, s);
                float inv = 1.f / sum;
                float* ao = outAl + ((size_t)(b0 + r) * TD + t) * TENC;
                for (int i = lane; i < TENC; i += 32) {
                    float a = s_sc[r][i] * inv;
                    s_sc[r][i] = a;
                    if (write_align) ao[i] = a;
                }
            }
        }
        __syncthreads();

        // attention context + build [attn_h, ctx] concat
        {
            int o = tid;
            float c0 = 0.f, c1 = 0.f;
            const float* e0 = enc + (size_t)b0 * TENC * DMODEL + o;
            const float* e1 = e0 + (size_t)TENC * DMODEL;
#pragma unroll 4
            for (int tt = 0; tt < TENC; ++tt) {
                c0 = fmaf(s_sc[0][tt], e0[(size_t)tt * DMODEL], c0);
                c1 = fmaf(s_sc[1][tt], e1[(size_t)tt * DMODEL], c1);
            }
            s_x[0][128 + o] = c0; s_x[1][128 + o] = c1;
            s_cat[0][256 + o] = c0; s_cat[1][256 + o] = c1;
            s_cat[0][o] = s_ah[0][o]; s_cat[1][o] = s_ah[1][o];
        }
        __syncthreads();

        // project to decoder input
        gemv2<256, 512, 0>(g_WprojT, s_cat[0], s_cat[1], b_proj, s_d[0], s_d[1]);
        __syncthreads();

        // decoder GRU 1 (+ residual)
        gemv2<768, 256, 0>(g_Wd1iT, s_d[0], s_d[1], b_d1i, s_gi[0], s_gi[1]);
        gemv2<768, 256, 0>(g_Wd1hT, s_h1[0], s_h1[1], b_d1h, s_gh[0], s_gh[1]);
        __syncthreads();
        for (int idx = tid; idx < 512; idx += TB) {
            int r = idx >> 8, o = idx & 255;
            float rg = sigmoidf_(s_gi[r][o] + s_gh[r][o]);
            float z = sigmoidf_(s_gi[r][256 + o] + s_gh[r][256 + o]);
            float n = tanhf(s_gi[r][512 + o] + rg * s_gh[r][512 + o]);
            s_h1[r][o] = (1.f - z) * n + z * s_h1[r][o];
        }
        __syncthreads();
        for (int idx = tid; idx < 512; idx += TB) {
            int r = idx >> 8, o = idx & 255;
            s_d[r][o] += s_h1[r][o];
        }
        __syncthreads();

        // decoder GRU 2 (+ residual)
        gemv2<768, 256, 0>(g_Wd2iT, s_d[0], s_d[1], b_d2i, s_gi[0], s_gi[1]);
        gemv2<768, 256, 0>(g_Wd2hT, s_h2[0], s_h2[1], b_d2h, s_gh[0], s_gh[1]);
        __syncthreads();
        for (int idx = tid; idx < 512; idx += TB) {
            int r = idx >> 8, o = idx & 255;
            float rg = sigmoidf_(s_gi[r][o] + s_gh[r][o]);
            float z = sigmoidf_(s_gi[r][256 + o] + s_gh[r][256 + o]);
            float n = tanhf(s_gi[r][512 + o] + rg * s_gh[r][512 + o]);
            s_h2[r][o] = (1.f - z) * n + z * s_h2[r][o];
        }
        __syncthreads();
        for (int idx = tid; idx < 512; idx += TB) {
            int r = idx >> 8, o = idx & 255;
            s_d[r][o] += s_h2[r][o];
        }
        __syncthreads();

        // mel projection -> straight to global output
        gemv2<400, 256, 0>(g_WmelT, s_d[0], s_d[1], b_mel,
                           outMel + ((size_t)b0 * TD + t) * INR,
                           outMel + ((size_t)(b0 + 1) * TD + t) * INR);
        __syncthreads();
    }
}

// ------------------------- launch -------------------------
extern "C" void kernel_launch(void* const* d_in, const int* in_sizes, int n_in,
                              void* d_out, int out_size) {
    const float* enc = (const float*)d_in[0];
    const float* inputs = (const float*)d_in[1];
    const int* memlen = (const int*)d_in[2];

    float *pWp1T, *pWp2T, *pWaihT, *pWahhT, *pWmemT, *pWqT, *pWprojT;
    float *pWd1iT, *pWd1hT, *pWd2iT, *pWd2hT, *pWmelT, *pPm;
    cudaGetSymbolAddress((void**)&pWp1T, g_Wp1T);
    cudaGetSymbolAddress((void**)&pWp2T, g_Wp2T);
    cudaGetSymbolAddress((void**)&pWaihT, g_WaihT);
    cudaGetSymbolAddress((void**)&pWahhT, g_WahhT);
    cudaGetSymbolAddress((void**)&pWmemT, g_WmemT);
    cudaGetSymbolAddress((void**)&pWqT, g_WqT);
    cudaGetSymbolAddress((void**)&pWprojT, g_WprojT);
    cudaGetSymbolAddress((void**)&pWd1iT, g_Wd1iT);
    cudaGetSymbolAddress((void**)&pWd1hT, g_Wd1hT);
    cudaGetSymbolAddress((void**)&pWd2iT, g_Wd2iT);
    cudaGetSymbolAddress((void**)&pWd2hT, g_Wd2hT);
    cudaGetSymbolAddress((void**)&pWmelT, g_WmelT);
    cudaGetSymbolAddress((void**)&pPm, g_pm);

    auto T = [&](const void* src, float* dst, int O, int K) {
        transpose_kernel<<<(O * K + 255) / 256, 256>>>((const float*)src, dst, O, K);
    };
    T(d_in[3], pWp1T, 256, 400);    // prenet_W1
    T(d_in[5], pWp2T, 128, 256);    // prenet_W2
    T(d_in[7], pWaihT, 768, 384);   // attn_Wih
    T(d_in[9], pWahhT, 768, 256);   // attn_Whh
    T(d_in[11], pWmemT, 256, 256);  // mem_W
    T(d_in[12], pWqT, 256, 256);    // query_W
    T(d_in[14], pWprojT, 256, 512); // proj_in_W
    T(d_in[16], pWd1iT, 768, 256);  // dec1_Wih
    T(d_in[18], pWd1hT, 768, 256);  // dec1_Whh
    T(d_in[20], pWd2iT, 768, 256);  // dec2_Wih
    T(d_in[22], pWd2hT, 768, 256);  // dec2_Whh
    T(d_in[24], pWmelT, 400, 256);  // mel_W

    pm_kernel<<<BATCH * TENC / 2, TB>>>(enc, pPm);

    int write_align = (out_size >= BATCH * TD * (INR + TENC)) ? 1 : 0;

    decoder_kernel<<<BATCH / 2, TB>>>(
        enc, inputs, memlen,
        (const float*)d_in[4], (const float*)d_in[6],
        (const float*)d_in[8], (const float*)d_in[10],
        (const float*)d_in[13],
        (const float*)d_in[15],
        (const float*)d_in[17], (const float*)d_in[19],
        (const float*)d_in[21], (const float*)d_in[23],
        (const float*)d_in[25],
        (float*)d_out, write_align);
}

// round 4
// speedup vs baseline: 2.7151x; 2.6543x over previous
#include <cuda_runtime.h>
#include <cuda_fp16.h>
#include <cstdint>
#include <cstddef>

#define TB 256
#define BATCH 256
#define TENC 200
#define TD 200
#define DMODEL 256
#define INR 400

// ------------------------- persistent device scratch -------------------------
__device__ float g_pm[BATCH * TENC * DMODEL];   // processed_memory (52 MB, fp32)

// fp16 weights, natural [O][K] layout (k contiguous per output row)
__device__ __half g_hWp1[256 * 400];
__device__ __half g_hWp2[128 * 256];
__device__ __half g_hWaih[768 * 384];
__device__ __half g_hWahh[768 * 256];
__device__ __half g_hWmem[256 * 256];
__device__ __half g_hWq[256 * 256];
__device__ __half g_hWproj[256 * 512];
__device__ __half g_hWd1i[768 * 256];
__device__ __half g_hWd1h[768 * 256];
__device__ __half g_hWd2i[768 * 256];
__device__ __half g_hWd2h[768 * 256];
__device__ __half g_hWmel[400 * 256];

// ------------------------- helpers -------------------------
__device__ __forceinline__ float tanh_approx(float x) {
    float y;
    asm("tanh.approx.f32 %0, %1;" : "=f"(y) : "f"(x));
    return y;
}
__device__ __forceinline__ float sigmoidf_(float x) {
    return 1.0f / (1.0f + __expf(-x));
}

// ------------------------- weight convert (1 launch, 12 matrices) ------------
struct CvtArgs {
    const float* src[12];
    __half* dst[12];
    int n[12];
};

__global__ void cvt_kernel(CvtArgs a) {
    int j = blockIdx.y;
    int n = a.n[j];
    const float* __restrict__ s = a.src[j];
    __half* __restrict__ d = a.dst[j];
    for (int i = blockIdx.x * blockDim.x + threadIdx.x; i < n;
         i += gridDim.x * blockDim.x)
        d[i] = __float2half_rn(s[i]);
}

// ------------------------- processed memory --------------------------------
// pm[row][o] = dot(mem_W[o][:], enc[row][:]) ; 16 rows per block
#define PM_ROWS 16
__global__ void __launch_bounds__(TB) pm_kernel(const float* __restrict__ enc,
                                                float* __restrict__ pm) {
    __shared__ __align__(16) float se[PM_ROWS][DMODEL];
    size_t row0 = (size_t)blockIdx.x * PM_ROWS;
    for (int i = threadIdx.x; i < PM_ROWS * DMODEL; i += TB)
        se[i >> 8][i & 255] = enc[row0 * DMODEL + i];
    __syncthreads();

    int o = threadIdx.x;  // 256 outputs
    float acc[PM_ROWS];
#pragma unroll
    for (int r = 0; r < PM_ROWS; ++r) acc[r] = 0.f;
    const uint4* __restrict__ W4 =
        reinterpret_cast<const uint4*>(g_hWmem + (size_t)o * DMODEL);
#pragma unroll 4
    for (int k8 = 0; k8 < DMODEL / 8; ++k8) {
        uint4 w = __ldg(&W4[k8]);
        float2 f0 = __half22float2(*reinterpret_cast<__half2*>(&w.x));
        float2 f1 = __half22float2(*reinterpret_cast<__half2*>(&w.y));
        float2 f2 = __half22float2(*reinterpret_cast<__half2*>(&w.z));
        float2 f3 = __half22float2(*reinterpret_cast<__half2*>(&w.w));
#pragma unroll
        for (int r = 0; r < PM_ROWS; ++r) {
            const float* e = &se[r][k8 * 8];
            float a = acc[r];
            a = fmaf(f0.x, e[0], a); a = fmaf(f0.y, e[1], a);
            a = fmaf(f1.x, e[2], a); a = fmaf(f1.y, e[3], a);
            a = fmaf(f2.x, e[4], a); a = fmaf(f2.y, e[5], a);
            a = fmaf(f3.x, e[6], a); a = fmaf(f3.y, e[7], a);
            acc[r] = a;
        }
    }
#pragma unroll
    for (int r = 0; r < PM_ROWS; ++r)
        pm[(row0 + r) * DMODEL + o] = acc[r];
}

// ------------------------- dual-row fp16 dot -------------------------------
// Wrow: fp16 [K] contiguous. Returns (row0, row1) dots in fp32.
template <int K>
__device__ __forceinline__ float2 dot2(const __half* __restrict__ Wrow,
                                       const float* __restrict__ x0,
                                       const float* __restrict__ x1) {
    const uint4* __restrict__ W4 = reinterpret_cast<const uint4*>(Wrow);
    const float4* __restrict__ X0 = reinterpret_cast<const float4*>(x0);
    const float4* __restrict__ X1 = reinterpret_cast<const float4*>(x1);
    float a = 0.f, b = 0.f;
#pragma unroll 8
    for (int i = 0; i < K / 8; ++i) {
        uint4 w = __ldg(&W4[i]);
        float2 f0 = __half22float2(*reinterpret_cast<__half2*>(&w.x));
        float2 f1 = __half22float2(*reinterpret_cast<__half2*>(&w.y));
        float2 f2 = __half22float2(*reinterpret_cast<__half2*>(&w.z));
        float2 f3 = __half22float2(*reinterpret_cast<__half2*>(&w.w));
        float4 xa0 = X0[2 * i], xa1 = X0[2 * i + 1];
        float4 xb0 = X1[2 * i], xb1 = X1[2 * i + 1];
        a = fmaf(f0.x, xa0.x, a); b = fmaf(f0.x, xb0.x, b);
        a = fmaf(f0.y, xa0.y, a); b = fmaf(f0.y, xb0.y, b);
        a = fmaf(f1.x, xa0.z, a); b = fmaf(f1.x, xb0.z, b);
        a = fmaf(f1.y, xa0.w, a); b = fmaf(f1.y, xb0.w, b);
        a = fmaf(f2.x, xa1.x, a); b = fmaf(f2.x, xb1.x, b);
        a = fmaf(f2.y, xa1.y, a); b = fmaf(f2.y, xb1.y, b);
        a = fmaf(f3.x, xa1.z, a); b = fmaf(f3.x, xb1.z, b);
        a = fmaf(f3.y, xa1.w, a); b = fmaf(f3.y, xb1.w, b);
    }
    return make_float2(a, b);
}

// ------------------------- main persistent decoder -------------------------
__global__ void __launch_bounds__(TB) decoder_kernel(
    const float* __restrict__ enc, const float* __restrict__ inputs,
    const int* __restrict__ memlen,
    const float* __restrict__ b_p1, const float* __restrict__ b_p2,
    const float* __restrict__ b_aih, const float* __restrict__ b_ahh,
    const float* __restrict__ vW,
    const float* __restrict__ b_proj,
    const float* __restrict__ b_d1i, const float* __restrict__ b_d1h,
    const float* __restrict__ b_d2i, const float* __restrict__ b_d2h,
    const float* __restrict__ b_mel,
    float* __restrict__ out, int write_align) {
    __shared__ __align__(16) float s_in[2][400];
    __shared__ __align__(16) float s_p1[2][256];
    __shared__ __align__(16) float s_x[2][384];   // [0:128)=prenet2, [128:384)=ctx
    __shared__ __align__(16) float s_ah[2][256];
    __shared__ __align__(16) float s_h1[2][256];
    __shared__ __align__(16) float s_h2[2][256];
    __shared__ __align__(16) float s_q[2][256];
    __shared__ __align__(16) float s_gi[2][768];  // also float4 scratch (1536 fl)
    __shared__ __align__(16) float s_gh[2][768];
    __shared__ __align__(16) float s_cat[2][512];
    __shared__ __align__(16) float s_d[2][256];
    __shared__ __align__(16) float s_sc[2][TENC];
    __shared__ __align__(16) float s_v[256];

    const int tid = threadIdx.x;
    const int b0 = blockIdx.x * 2;
    const int len0 = memlen[b0];
    const int len1 = memlen[b0 + 1];

    for (int i = tid; i < 256; i += TB) {
        s_ah[0][i] = 0.f; s_ah[1][i] = 0.f;
        s_h1[0][i] = 0.f; s_h1[1][i] = 0.f;
        s_h2[0][i] = 0.f; s_h2[1][i] = 0.f;
        s_x[0][128 + i] = 0.f; s_x[1][128 + i] = 0.f;
        s_v[i] = vW[i];
    }
    __syncthreads();

    float* outMel = out;
    float* outAl = out + (size_t)BATCH * TD * INR;

    for (int t = 0; t < TD; ++t) {
        // ---- teacher-forced input frame group ----
        if (t == 0) {
            for (int i = tid; i < INR; i += TB) { s_in[0][i] = 0.f; s_in[1][i] = 0.f; }
        } else {
            const float* p0 = inputs + ((size_t)b0 * 1000 + (size_t)(t - 1) * 5) * 80;
            const float* p1 = inputs + ((size_t)(b0 + 1) * 1000 + (size_t)(t - 1) * 5) * 80;
            for (int i = tid; i < INR; i += TB) { s_in[0][i] = p0[i]; s_in[1][i] = p1[i]; }
        }
        __syncthreads();

        // ---- prenet layer 1 (O=256, K=400) ----
        {
            float2 r = dot2<400>(g_hWp1 + (size_t)tid * 400, s_in[0], s_in[1]);
            float bb = b_p1[tid];
            s_p1[0][tid] = fmaxf(r.x + bb, 0.f);
            s_p1[1][tid] = fmaxf(r.y + bb, 0.f);
        }
        __syncthreads();

        // ---- prenet layer 2 (O=128, K=256) with 2-way K split ----
        {
            int o = tid & 127, half = tid >> 7;
            float2 r = dot2<128>(g_hWp2 + (size_t)o * 256 + half * 128,
                                 s_p1[0] + half * 128, s_p1[1] + half * 128);
            s_gi[0][tid] = r.x;  // scratch
            s_gi[1][tid] = r.y;
        }
        __syncthreads();
        if (tid < 128) {
            float bb = b_p2[tid];
            s_x[0][tid] = fmaxf(s_gi[0][tid] + s_gi[0][128 + tid] + bb, 0.f);
            s_x[1][tid] = fmaxf(s_gi[1][tid] + s_gi[1][128 + tid] + bb, 0.f);
        }
        __syncthreads();

        // ---- attention GRU gates (gi: 768xK384, gh: 768xK256) ----
#pragma unroll
        for (int it = 0; it < 3; ++it) {
            int o = it * TB + tid;
            float2 r = dot2<384>(g_hWaih + (size_t)o * 384, s_x[0], s_x[1]);
            float bb = b_aih[o];
            s_gi[0][o] = r.x + bb; s_gi[1][o] = r.y + bb;
        }
#pragma unroll
        for (int it = 0; it < 3; ++it) {
            int o = it * TB + tid;
            float2 r = dot2<256>(g_hWahh + (size_t)o * 256, s_ah[0], s_ah[1]);
            float bb = b_ahh[o];
            s_gh[0][o] = r.x + bb; s_gh[1][o] = r.y + bb;
        }
        __syncthreads();
        // nonlinearity -> attn hidden
        for (int idx = tid; idx < 512; idx += TB) {
            int r = idx >> 8, o = idx & 255;
            float rg = sigmoidf_(s_gi[r][o] + s_gh[r][o]);
            float z = sigmoidf_(s_gi[r][256 + o] + s_gh[r][256 + o]);
            float n = tanhf(s_gi[r][512 + o] + rg * s_gh[r][512 + o]);
            s_ah[r][o] = (1.f - z) * n + z * s_ah[r][o];
        }
        __syncthreads();

        // ---- query projection (O=256, K=256, no bias) ----
        {
            float2 r = dot2<256>(g_hWq + (size_t)tid * 256, s_ah[0], s_ah[1]);
            s_q[0][tid] = r.x; s_q[1][tid] = r.y;
        }
        __syncthreads();

        // ---- Bahdanau scores ----
        {
            int wid = tid >> 5, lane = tid & 31;
            for (int task = wid; task < 2 * TENC; task += 8) {
                int r = task & 1, tt = task >> 1;
                const float4* P = reinterpret_cast<const float4*>(
                    g_pm + ((size_t)(b0 + r) * TENC + tt) * DMODEL);
                const float4* Q = reinterpret_cast<const float4*>(s_q[r]);
                const float4* V = reinterpret_cast<const float4*>(s_v);
                float acc = 0.f;
#pragma unroll
                for (int u = 0; u < 2; ++u) {
                    int k4 = u * 32 + lane;
                    float4 p = __ldg(&P[k4]);
                    float4 q = Q[k4], v = V[k4];
                    acc += v.x * tanh_approx(p.x + q.x);
                    acc += v.y * tanh_approx(p.y + q.y);
                    acc += v.z * tanh_approx(p.z + q.z);
                    acc += v.w * tanh_approx(p.w + q.w);
                }
#pragma unroll
                for (int s = 16; s; s >>= 1) acc += __shfl_xor_sync(0xffffffffu, acc, s);
                if (lane == 0) {
                    int L = r ? len1 : len0;
                    s_sc[r][tt] = (tt < L) ? acc : -1e9f;
                }
            }
        }
        __syncthreads();

        // ---- softmax + alignment output ----
        {
            int wid = tid >> 5, lane = tid & 31;
            if (wid < 2) {
                int r = wid;
                float m = -1e30f;
                for (int i = lane; i < TENC; i += 32) m = fmaxf(m, s_sc[r][i]);
#pragma unroll
                for (int s = 16; s; s >>= 1) m = fmaxf(m, __shfl_xor_sync(0xffffffffu, m, s));
                float sum = 0.f;
                for (int i = lane; i < TENC; i += 32) {
                    float e = __expf(s_sc[r][i] - m);
                    s_sc[r][i] = e;
                    sum += e;
                }
#pragma unroll
                for (int s = 16; s; s >>= 1) sum += __shfl_xor_sync(0xffffffffu, sum, s);
                float inv = 1.f / sum;
                float* ao = outAl + ((size_t)(b0 + r) * TD + t) * TENC;
                for (int i = lane; i < TENC; i += 32) {
                    float a = s_sc[r][i] * inv;
                    s_sc[r][i] = a;
                    if (write_align) ao[i] = a;
                }
            }
        }
        __syncthreads();

        // ---- attention context (float4 x 2-way T split) ----
        {
            int g = tid & 63, row = (tid >> 6) & 1, th = tid >> 7;
            const float4* E = reinterpret_cast<const float4*>(
                                  enc + (size_t)(b0 + row) * TENC * DMODEL) + g;
            const float* sc = s_sc[row];
            float4 acc = make_float4(0.f, 0.f, 0.f, 0.f);
            int tt0 = th * 100;
#pragma unroll 8
            for (int tt = tt0; tt < tt0 + 100; ++tt) {
                float a = sc[tt];
                float4 e = __ldg(&E[(size_t)tt * 64]);
                acc.x = fmaf(a, e.x, acc.x);
                acc.y = fmaf(a, e.y, acc.y);
                acc.z = fmaf(a, e.z, acc.z);
                acc.w = fmaf(a, e.w, acc.w);
            }
            float4* scr = reinterpret_cast<float4*>(&s_gi[0][0]);
            scr[tid] = acc;
        }
        __syncthreads();
        {
            float4* scr = reinterpret_cast<float4*>(&s_gi[0][0]);
            if (tid < 128) {
                int row = (tid >> 6) & 1, g = tid & 63;
                float4 a = scr[tid], b = scr[tid + 128];
                a.x += b.x; a.y += b.y; a.z += b.z; a.w += b.w;
                reinterpret_cast<float4*>(&s_x[row][128])[g] = a;
                reinterpret_cast<float4*>(&s_cat[row][256])[g] = a;
            } else {
                int row = (tid >> 6) & 1, g = tid & 63;
                reinterpret_cast<float4*>(&s_cat[row][0])[g] =
                    reinterpret_cast<float4*>(&s_ah[row][0])[g];
            }
        }
        __syncthreads();

        // ---- project to decoder input (O=256, K=512) ----
        {
            float2 r = dot2<512>(g_hWproj + (size_t)tid * 512, s_cat[0], s_cat[1]);
            float bb = b_proj[tid];
            s_d[0][tid] = r.x + bb; s_d[1][tid] = r.y + bb;
        }
        __syncthreads();

        // ---- decoder GRU 1 ----
#pragma unroll
        for (int it = 0; it < 3; ++it) {
            int o = it * TB + tid;
            float2 r = dot2<256>(g_hWd1i + (size_t)o * 256, s_d[0], s_d[1]);
            float bb = b_d1i[o];
            s_gi[0][o] = r.x + bb; s_gi[1][o] = r.y + bb;
        }
#pragma unroll
        for (int it = 0; it < 3; ++it) {
            int o = it * TB + tid;
            float2 r = dot2<256>(g_hWd1h + (size_t)o * 256, s_h1[0], s_h1[1]);
            float bb = b_d1h[o];
            s_gh[0][o] = r.x + bb; s_gh[1][o] = r.y + bb;
        }
        __syncthreads();
        for (int idx = tid; idx < 512; idx += TB) {
            int r = idx >> 8, o = idx & 255;
            float rg = sigmoidf_(s_gi[r][o] + s_gh[r][o]);
            float z = sigmoidf_(s_gi[r][256 + o] + s_gh[r][256 + o]);
            float n = tanhf(s_gi[r][512 + o] + rg * s_gh[r][512 + o]);
            float h = (1.f - z) * n + z * s_h1[r][o];
            s_h1[r][o] = h;
            s_d[r][o] += h;  // residual
        }
        __syncthreads();

        // ---- decoder GRU 2 ----
#pragma unroll
        for (int it = 0; it < 3; ++it) {
            int o = it * TB + tid;
            float2 r = dot2<256>(g_hWd2i + (size_t)o * 256, s_d[0], s_d[1]);
            float bb = b_d2i[o];
            s_gi[0][o] = r.x + bb; s_gi[1][o] = r.y + bb;
        }
#pragma unroll
        for (int it = 0; it < 3; ++it) {
            int o = it * TB + tid;
            float2 r = dot2<256>(g_hWd2h + (size_t)o * 256, s_h2[0], s_h2[1]);
            float bb = b_d2h[o];
            s_gh[0][o] = r.x + bb; s_gh[1][o] = r.y + bb;
        }
        __syncthreads();
        for (int idx = tid; idx < 512; idx += TB) {
            int r = idx >> 8, o = idx & 255;
            float rg = sigmoidf_(s_gi[r][o] + s_gh[r][o]);
            float z = sigmoidf_(s_gi[r][256 + o] + s_gh[r][256 + o]);
            float n = tanhf(s_gi[r][512 + o] + rg * s_gh[r][512 + o]);
            float h = (1.f - z) * n + z * s_h2[r][o];
            s_h2[r][o] = h;
            s_d[r][o] += h;  // residual
        }
        __syncthreads();

        // ---- mel projection (O=400, K=256) -> global ----
        {
            float* o0 = outMel + ((size_t)b0 * TD + t) * INR;
            float* o1 = outMel + ((size_t)(b0 + 1) * TD + t) * INR;
            for (int o = tid; o < INR; o += TB) {
                float2 r = dot2<256>(g_hWmel + (size_t)o * 256, s_d[0], s_d[1]);
                float bb = b_mel[o];
                o0[o] = r.x + bb;
                o1[o] = r.y + bb;
            }
        }
        __syncthreads();
    }
}

// ------------------------- launch -------------------------
extern "C" void kernel_launch(void* const* d_in, const int* in_sizes, int n_in,
                              void* d_out, int out_size) {
    const float* enc = (const float*)d_in[0];
    const float* inputs = (const float*)d_in[1];
    const int* memlen = (const int*)d_in[2];

    __half *hWp1, *hWp2, *hWaih, *hWahh, *hWmem, *hWq, *hWproj;
    __half *hWd1i, *hWd1h, *hWd2i, *hWd2h, *hWmel;
    float* pPm;
    cudaGetSymbolAddress((void**)&hWp1, g_hWp1);
    cudaGetSymbolAddress((void**)&hWp2, g_hWp2);
    cudaGetSymbolAddress((void**)&hWaih, g_hWaih);
    cudaGetSymbolAddress((void**)&hWahh, g_hWahh);
    cudaGetSymbolAddress((void**)&hWmem, g_hWmem);
    cudaGetSymbolAddress((void**)&hWq, g_hWq);
    cudaGetSymbolAddress((void**)&hWproj, g_hWproj);
    cudaGetSymbolAddress((void**)&hWd1i, g_hWd1i);
    cudaGetSymbolAddress((void**)&hWd1h, g_hWd1h);
    cudaGetSymbolAddress((void**)&hWd2i, g_hWd2i);
    cudaGetSymbolAddress((void**)&hWd2h, g_hWd2h);
    cudaGetSymbolAddress((void**)&hWmel, g_hWmel);
    cudaGetSymbolAddress((void**)&pPm, g_pm);

    CvtArgs a;
    a.src[0] = (const float*)d_in[3];  a.dst[0] = hWp1;  a.n[0] = 256 * 400;
    a.src[1] = (const float*)d_in[5];  a.dst[1] = hWp2;  a.n[1] = 128 * 256;
    a.src[2] = (const float*)d_in[7];  a.dst[2] = hWaih; a.n[2] = 768 * 384;
    a.src[3] = (const float*)d_in[9];  a.dst[3] = hWahh; a.n[3] = 768 * 256;
    a.src[4] = (const float*)d_in[11]; a.dst[4] = hWmem; a.n[4] = 256 * 256;
    a.src[5] = (const float*)d_in[12]; a.dst[5] = hWq;   a.n[5] = 256 * 256;
    a.src[6] = (const float*)d_in[14]; a.dst[6] = hWproj;a.n[6] = 256 * 512;
    a.src[7] = (const float*)d_in[16]; a.dst[7] = hWd1i; a.n[7] = 768 * 256;
    a.src[8] = (const float*)d_in[18]; a.dst[8] = hWd1h; a.n[8] = 768 * 256;
    a.src[9] = (const float*)d_in[20]; a.dst[9] = hWd2i; a.n[9] = 768 * 256;
    a.src[10] = (const float*)d_in[22]; a.dst[10] = hWd2h; a.n[10] = 768 * 256;
    a.src[11] = (const float*)d_in[24]; a.dst[11] = hWmel; a.n[11] = 400 * 256;

    dim3 cgrid(288, 12);
    cvt_kernel<<<cgrid, TB>>>(a);

    pm_kernel<<<BATCH * TENC / PM_ROWS, TB>>>(enc, pPm);

    int write_align = (out_size >= BATCH * TD * (INR + TENC)) ? 1 : 0;

    decoder_kernel<<<BATCH / 2, TB>>>(
        enc, inputs, memlen,
        (const float*)d_in[4], (const float*)d_in[6],
        (const float*)d_in[8], (const float*)d_in[10],
        (const float*)d_in[13],
        (const float*)d_in[15],
        (const float*)d_in[17], (const float*)d_in[19],
        (const float*)d_in[21], (const float*)d_in[23],
        (const float*)d_in[25],
        (float*)d_out, write_align);
}